// round 15
// baseline (speedup 1.0000x reference)
#include <cuda_runtime.h>
#include <cuda_bf16.h>

#define NSIDE 256
#define NB    128     // blocks; each owns 2 adjacent lines
#define NT    1024    // 2 lines x 16 scanner warps
#define NTL   512     // threads per line
#define LAM   0.05f   // STEP = ALPHA/2
#define TOLV  0.01f
#define NITER 35
#define HALF  (NSIDE / 2)
#define SEG   16      // elements per speculative segment
#define NSEGS (HALF / SEG)   // 8 per direction
#define BIGK  (NSIDE + 8)

// Cross-block exchange buffers (8B-aligned for packed float2 stores).
__device__ __align__(8) float g_y [NSIDE * NSIDE];
__device__ __align__(8) float g_xT[NSIDE * NSIDE];

// Grid barrier: monotone arrival counter + release word g_ep = 2*epoch | stop.
__device__ unsigned          g_cnt;
__device__ volatile unsigned g_ep;
__device__ int               g_accbits;

struct TVState {
    int k, k0, kminus, kplus;
    float vmin, vmax, umin, umax, ynext;
};

template<bool FWD>
__device__ __forceinline__ float ldy(const float* __restrict__ s, int i) {
    return FWD ? s[i] : s[NSIDE - 1 - i];
}
template<bool FWD>
__device__ __forceinline__ void sto(float* __restrict__ out, int i, float v) {
    if (FWD) out[i] = v; else out[NSIDE - 1 - i] = v;
}

// Fresh Condat state positioned at `pos` (pos < NSIDE-1).
template<bool FWD>
__device__ __forceinline__ void init_state_at(const float* __restrict__ s,
                                              TVState& t, int pos)
{
    float y0 = ldy<FWD>(s, pos), y1 = ldy<FWD>(s, pos + 1);
    t.k = pos; t.k0 = pos; t.kminus = pos; t.kplus = pos;
    t.vmin = y0 - LAM; t.vmax = y0 + LAM;
    t.umin = LAM; t.umax = -LAM;
    t.ynext = y1;
}

// Exact 1D TV prox (Condat 2013), resumable, fused jump path.
// MODE 0: plain. MODE 1: record restart (pos,dir) into log.
// MODE 2: after each restart at pos p with dir d, if log[p]==d the state
//         provably equals the spec scanner's post-restart state -> return 1.
template<bool FWD, int MODE>
__device__ int tv_scan(const float* __restrict__ s, float* __restrict__ out,
                       const float* __restrict__ rcp, TVState& t,
                       int kstop, int k0stop, unsigned char* log)
{
    const float lam = LAM, mlam = -LAM, twolam = 2.0f * LAM;
    for (;;) {
        if (t.k0 >= k0stop) return 0;
        while (t.k == NSIDE - 1) {            // termination (kstop==NSIDE only)
            if (t.umin < 0.0f) {
                do { sto<FWD>(out, t.k0++, t.vmin); } while (t.k0 <= t.kminus);
                t.k = t.k0; t.kminus = t.k0;
                t.vmin = ldy<FWD>(s, t.k);
                t.umin = lam;
                t.umax = t.vmin + lam - t.vmax;
            } else if (t.umax > 0.0f) {
                do { sto<FWD>(out, t.k0++, t.vmax); } while (t.k0 <= t.kplus);
                t.k = t.k0; t.kplus = t.k0;
                t.vmax = ldy<FWD>(s, t.k);
                t.umax = mlam;
                t.umin = t.vmax - lam - t.vmin;
            } else {
                t.vmin += t.umin * rcp[t.k - t.k0];
                do { sto<FWD>(out, t.k0++, t.vmin); } while (t.k0 <= t.k);
                t.k0 = BIGK;                   // done
                return 0;
            }
            t.ynext = ldy<FWD>(s, t.k + 1);
            if (t.k0 >= k0stop) return 0;
        }
        if (t.k >= kstop) return 0;
        float yspec = ldy<FWD>(s, t.k + 2);   // speculative prefetch (padded)
        float a  = t.umin + (t.ynext - t.vmin);
        float bb = t.umax + (t.ynext - t.vmax);
        bool neg = (a < mlam);                // priority matches else-if order
        if (neg || (bb > lam)) {              // fused jump path (common ~90%)
            float ev = neg ? t.vmin : t.vmax;
            int   kl = neg ? t.kminus : t.kplus;
            do { sto<FWD>(out, t.k0++, ev); } while (t.k0 <= kl);
            bool fast = (t.k0 == t.k + 1);    // restart value already in ynext?
            t.k = t.k0; t.kminus = t.k0; t.kplus = t.k0;
            float nv = fast ? t.ynext : ldy<FWD>(s, t.k0);
            t.ynext  = fast ? yspec   : ldy<FWD>(s, t.k0 + 1);
            t.vmin = neg ? nv : nv - twolam;
            t.vmax = neg ? nv + twolam : nv;
            t.umin = lam; t.umax = mlam;
            unsigned char d = neg ? 1 : 2;
            if (MODE == 1) log[t.k0] = d;
            if (MODE == 2) { if (log[t.k0] == d) return 1; }
        } else {                              // no jump
            t.k++;
            t.umin = a; t.umax = bb;
            if (a >= lam)   { t.vmin += (a - lam)  * rcp[t.k - t.k0]; t.umin = lam;  t.kminus = t.k; }
            if (bb <= mlam) { t.vmax += (bb + lam) * rcp[t.k - t.k0]; t.umax = mlam; t.kplus  = t.k; }
            t.ynext = yspec;
        }
    }
}

// Grid barrier: monotone counter, thread0-only fences, folded residual commit.
__device__ __forceinline__ bool gridbar(unsigned& ep, bool doCommit,
                                        float* swm, int* sstop)
{
    __syncthreads();                       // block writes + swm visible
    ep += 1;
    if (threadIdx.x < 32) {
        float mm = 0.0f;
        if (doCommit) {
            mm = swm[threadIdx.x];         // NT/32 == 32 slots exactly
#pragma unroll
            for (int off = 16; off; off >>= 1)
                mm = fmaxf(mm, __shfl_xor_sync(0xffffffffu, mm, off));
        }
        if (threadIdx.x == 0) {
            if (doCommit)
                atomicMax(&g_accbits, __float_as_int(mm));   // no return -> RED
            __threadfence();               // cumulative release
            unsigned old = atomicAdd(&g_cnt, 1u);
            unsigned target = ep * (unsigned)NB;
            unsigned rel;
            if (old == target - 1u) {      // last arriver releases
                __threadfence();           // acquire all blocks' writes
                unsigned stop = 0;
                if (doCommit) {
                    stop = (__int_as_float(g_accbits) < TOLV) ? 1u : 0u;
                    g_accbits = 0;
                }
                __threadfence();
                rel = ep * 2u + stop;
                g_ep = rel;
            } else {
                do { rel = g_ep; } while ((int)(rel - ep * 2u) < 0);
                __threadfence();           // cumulative acquire
            }
            *sstop = (int)(rel & 1u);
        }
    }
    __syncthreads();                       // propagate visibility + sstop
    return *sstop != 0;
}

struct LineBlk {
    float s[NSIDE + 2];
    float o[NSIDE];
    float ob[NSIDE];
    float p[NSIDE];
    float q[NSIDE];
    unsigned char f_log[HALF + 2];
    unsigned char b_log[HALF + 2];
    TVState sf_end[NSEGS], sb_end[NSEGS];   // index 1..NSEGS-1 used
    int f_done[NSEGS];                      // per-segment publish flags
    int b_done[NSEGS];
    int se_done;
    int se_b;
};

#define VOL(x) (*(volatile int*)&(x))

__device__ __forceinline__ float merged(const LineBlk& L, int i)
{
    return (i >= L.se_b) ? L.ob[i] : L.o[i];
}

// One full line solve using 16 scanner threads (one per warp within the line's
// 512 threads). No intra-stage __syncthreads: spec scanners publish per-segment
// flags; the exact checkers pipeline behind them.
__device__ __forceinline__ void solve_line(LineBlk& sh, const float* rcp,
                                           int lt, TVState& tf, TVState& tb)
{
    const int w = lt >> 5;
    if ((lt & 31) != 0) return;

    if (w == 0) {
        // ---- exact forward [0, SEG), then pipelined coupling fixup ----
        init_state_at<true>(sh.s, tf, 0);
        tv_scan<true, 0>(sh.s, sh.o, rcp, tf, SEG, BIGK, 0);
        while (tf.k < HALF) {
            int j = tf.k / SEG;                    // 1..NSEGS-1
            while (!VOL(sh.f_done[j])) { }
            __threadfence_block();
            if (tv_scan<true, 2>(sh.s, sh.o, rcp, tf, (j + 1) * SEG, BIGK, sh.f_log)) {
                int jj = (tf.k0 - 1) / SEG;        // owner of matched restart
                tf = sh.sf_end[jj];                // provably equal: adopt tail
            }
        }
        // ---- stage C: close the middle gap (needs backward frontier) ----
        while (!VOL(sh.se_done)) { }
        __threadfence_block();
        tv_scan<true, 0>(sh.s, sh.o, rcp, tf, NSIDE, VOL(sh.se_b), 0);
    } else if (w < NSEGS) {
        // ---- speculative forward, segment w ----
        TVState t; init_state_at<true>(sh.s, t, w * SEG);
        tv_scan<true, 1>(sh.s, sh.o, rcp, t, (w + 1) * SEG, BIGK, sh.f_log);
        sh.sf_end[w] = t;
        __threadfence_block();
        VOL(sh.f_done[w]) = 1;
    } else if (w == NSEGS) {
        // ---- exact backward [0, SEG)b, then pipelined coupling fixup ----
        init_state_at<false>(sh.s, tb, 0);
        tv_scan<false, 0>(sh.s, sh.ob, rcp, tb, SEG, BIGK, 0);
        while (tb.k < HALF) {
            int j = tb.k / SEG;
            while (!VOL(sh.b_done[j])) { }
            __threadfence_block();
            if (tv_scan<false, 2>(sh.s, sh.ob, rcp, tb, (j + 1) * SEG, BIGK, sh.b_log)) {
                int jj = (tb.k0 - 1) / SEG;
                tb = sh.sb_end[jj];
            }
        }
        VOL(sh.se_b) = NSIDE - tb.k0;              // first finalized bwd position
        __threadfence_block();
        VOL(sh.se_done) = 1;
    } else {
        // ---- speculative backward, segment w-NSEGS ----
        int j = w - NSEGS;
        TVState t; init_state_at<false>(sh.s, t, j * SEG);
        tv_scan<false, 1>(sh.s, sh.ob, rcp, t, (j + 1) * SEG, BIGK, sh.b_log);
        sh.sb_end[j] = t;
        __threadfence_block();
        VOL(sh.b_done[j]) = 1;
    }
}

__global__ void __launch_bounds__(NT, 1)
tv2d_persistent(const float* __restrict__ X, float* __restrict__ x)
{
    __shared__ LineBlk sh[2];
    __shared__ float rcp_s[NSIDE];
    __shared__ float swm[NT / 32];
    __shared__ int sstop;
    const int tid  = threadIdx.x;
    const int line = tid >> 9;           // 0 or 1
    const int lt   = tid & (NTL - 1);    // tid within line
    const int lane = tid & 31;
    const int b    = blockIdx.x * 2 + line;   // owned column/row index
    const int b0   = blockIdx.x * 2;          // even base index (packed stores)
    const bool io  = (lt < NSIDE);
    const bool packer = (tid < NSIDE);   // line-0 io threads do packed stores
    unsigned ep = g_ep >> 1;             // unpack epoch (stable at launch)
    TVState tf, tb;
    LineBlk& L = sh[line];

    if (io) {
        L.p[lt] = 0.0f;
        L.q[lt] = 0.0f;
        if (line == 0) rcp_s[lt] = 1.0f / (float)(lt + 1);
    }
    if (lt == 0) { L.s[NSIDE] = 0.0f; L.s[NSIDE + 1] = 0.0f; }

    for (int it = 0; it < NITER; it++) {
        // ================= column phase: line owns column b =================
        if (io) {
            float xv = (it == 0) ? X[lt * NSIDE + b] : g_xT[b * NSIDE + lt];
            L.s[lt] = xv + L.p[lt];
            if (lt <= HALF - SEG) {       // clear restart logs [SEG, HALF]
                L.f_log[SEG + lt] = 0;
                L.b_log[SEG + lt] = 0;
            }
            if (lt < NSEGS) { L.f_done[lt] = 0; L.b_done[lt] = 0; }
            if (lt == 0)    { L.se_done = 0; }
        }
        __syncthreads();

        solve_line(L, rcp_s, lt, tf, tb);
        __syncthreads();

        if (io) {                         // own-line SMEM update
            L.p[lt] = L.s[lt] - merged(L, lt);
        }
        if (packer) {                     // packed transpose store (both lines)
            float2 v = make_float2(merged(sh[0], lt), merged(sh[1], lt));
            *reinterpret_cast<float2*>(&g_y[lt * NSIDE + b0]) = v;
        }
        gridbar(ep, false, swm, &sstop);

        // ================= row phase: line owns row b =======================
        if (io) {
            L.s[lt] = g_y[b * NSIDE + lt] + L.q[lt];
            if (lt <= HALF - SEG) {
                L.f_log[SEG + lt] = 0;
                L.b_log[SEG + lt] = 0;
            }
            if (lt < NSEGS) { L.f_done[lt] = 0; L.b_done[lt] = 0; }
            if (lt == 0)    { L.se_done = 0; }
        }
        __syncthreads();

        solve_line(L, rcp_s, lt, tf, tb);
        __syncthreads();

        float m = 0.0f;
        if (io) {
            float ov = merged(L, lt);
            float sv = L.s[lt];
            float qo = L.q[lt];
            L.q[lt] = sv - ov;
            x[b * NSIDE + lt] = ov;       // d_out (coalesced per line)
            m = fabsf((sv - qo) - ov);    // |y - x2|
        }
        if (packer) {                     // packed transposed mirror store
            float2 v = make_float2(merged(sh[0], lt), merged(sh[1], lt));
            *reinterpret_cast<float2*>(&g_xT[lt * NSIDE + b0]) = v;
        }
#pragma unroll
        for (int off = 16; off; off >>= 1)
            m = fmaxf(m, __shfl_xor_sync(0xffffffffu, m, off));
        if (lane == 0) swm[tid >> 5] = m;     // all 32 warps write a slot

        if (gridbar(ep, true, swm, &sstop)) break;   // DR converged
    }
}

extern "C" void kernel_launch(void* const* d_in, const int* in_sizes, int n_in,
                              void* d_out, int out_size)
{
    const float* X = (const float*)d_in[0];
    float* x = (float*)d_out;
    tv2d_persistent<<<NB, NT>>>(X, x);
}

// round 16
// speedup vs baseline: 1.1483x; 1.1483x over previous
#include <cuda_runtime.h>
#include <cuda_bf16.h>

#define NSIDE 256
#define NB    128     // blocks; each owns 2 lines
#define NT    1024    // 2 lines x 16 scanner warps
#define NTL   512     // threads per line
#define LAM   0.05f   // STEP = ALPHA/2
#define TOLV  0.01f
#define NITER 35
#define HALF  (NSIDE / 2)
#define SEG   16      // elements per speculative segment
#define NSEGS (HALF / SEG)   // 8 per direction
#define BIGK  (NSIDE + 8)

// Cross-block exchange buffers.
__device__ float g_y [NSIDE * NSIDE];
__device__ float g_xT[NSIDE * NSIDE];

// Grid barrier: monotone arrival counter + release word g_ep = 2*epoch | stop.
__device__ unsigned          g_cnt;
__device__ volatile unsigned g_ep;
__device__ int               g_accbits;

struct TVState {
    int k, k0, kminus, kplus;
    float vmin, vmax, umin, umax, ynext;
};

template<bool FWD>
__device__ __forceinline__ float ldy(const float* __restrict__ s, int i) {
    return FWD ? s[i] : s[NSIDE - 1 - i];
}
template<bool FWD>
__device__ __forceinline__ void sto(float* __restrict__ out, int i, float v) {
    if (FWD) out[i] = v; else out[NSIDE - 1 - i] = v;
}

// Fresh Condat state positioned at `pos` (pos < NSIDE-1).
template<bool FWD>
__device__ __forceinline__ void init_state_at(const float* __restrict__ s,
                                              TVState& t, int pos)
{
    float y0 = ldy<FWD>(s, pos), y1 = ldy<FWD>(s, pos + 1);
    t.k = pos; t.k0 = pos; t.kminus = pos; t.kplus = pos;
    t.vmin = y0 - LAM; t.vmax = y0 + LAM;
    t.umin = LAM; t.umax = -LAM;
    t.ynext = y1;
}

// Exact 1D TV prox (Condat 2013), resumable, fused jump path.
// MODE 0: plain. MODE 1: record restart (pos,dir) into log.
// MODE 2: after each restart at pos p with dir d, if log[p]==d the state
//         provably equals the spec scanner's post-restart state -> return 1.
template<bool FWD, int MODE>
__device__ int tv_scan(const float* __restrict__ s, float* __restrict__ out,
                       const float* __restrict__ rcp, TVState& t,
                       int kstop, int k0stop, unsigned char* log)
{
    const float lam = LAM, mlam = -LAM, twolam = 2.0f * LAM;
    for (;;) {
        if (t.k0 >= k0stop) return 0;
        while (t.k == NSIDE - 1) {            // termination (kstop==NSIDE only)
            if (t.umin < 0.0f) {
                do { sto<FWD>(out, t.k0++, t.vmin); } while (t.k0 <= t.kminus);
                t.k = t.k0; t.kminus = t.k0;
                t.vmin = ldy<FWD>(s, t.k);
                t.umin = lam;
                t.umax = t.vmin + lam - t.vmax;
            } else if (t.umax > 0.0f) {
                do { sto<FWD>(out, t.k0++, t.vmax); } while (t.k0 <= t.kplus);
                t.k = t.k0; t.kplus = t.k0;
                t.vmax = ldy<FWD>(s, t.k);
                t.umax = mlam;
                t.umin = t.vmax - lam - t.vmin;
            } else {
                t.vmin += t.umin * rcp[t.k - t.k0];
                do { sto<FWD>(out, t.k0++, t.vmin); } while (t.k0 <= t.k);
                t.k0 = BIGK;                   // done
                return 0;
            }
            t.ynext = ldy<FWD>(s, t.k + 1);
            if (t.k0 >= k0stop) return 0;
        }
        if (t.k >= kstop) return 0;
        float yspec = ldy<FWD>(s, t.k + 2);   // speculative prefetch (padded)
        float a  = t.umin + (t.ynext - t.vmin);
        float bb = t.umax + (t.ynext - t.vmax);
        bool neg = (a < mlam);                // priority matches else-if order
        if (neg || (bb > lam)) {              // fused jump path (common ~90%)
            float ev = neg ? t.vmin : t.vmax;
            int   kl = neg ? t.kminus : t.kplus;
            do { sto<FWD>(out, t.k0++, ev); } while (t.k0 <= kl);
            bool fast = (t.k0 == t.k + 1);    // restart value already in ynext?
            t.k = t.k0; t.kminus = t.k0; t.kplus = t.k0;
            float nv = fast ? t.ynext : ldy<FWD>(s, t.k0);
            t.ynext  = fast ? yspec   : ldy<FWD>(s, t.k0 + 1);
            t.vmin = neg ? nv : nv - twolam;
            t.vmax = neg ? nv + twolam : nv;
            t.umin = lam; t.umax = mlam;
            unsigned char d = neg ? 1 : 2;
            if (MODE == 1) log[t.k0] = d;
            if (MODE == 2) { if (log[t.k0] == d) return 1; }
        } else {                              // no jump
            t.k++;
            t.umin = a; t.umax = bb;
            if (a >= lam)   { t.vmin += (a - lam)  * rcp[t.k - t.k0]; t.umin = lam;  t.kminus = t.k; }
            if (bb <= mlam) { t.vmax += (bb + lam) * rcp[t.k - t.k0]; t.umax = mlam; t.kplus  = t.k; }
            t.ynext = yspec;
        }
    }
}

// Grid barrier: monotone counter, thread0-only fences, folded residual commit.
__device__ __forceinline__ bool gridbar(unsigned& ep, bool doCommit,
                                        float* swm, int* sstop)
{
    __syncthreads();                       // block writes + swm visible
    ep += 1;
    if (threadIdx.x < 32) {
        float mm = 0.0f;
        if (doCommit) {
            mm = swm[threadIdx.x];         // NT/32 == 32 slots exactly
#pragma unroll
            for (int off = 16; off; off >>= 1)
                mm = fmaxf(mm, __shfl_xor_sync(0xffffffffu, mm, off));
        }
        if (threadIdx.x == 0) {
            if (doCommit)
                atomicMax(&g_accbits, __float_as_int(mm));   // no return -> RED
            __threadfence();               // cumulative release
            unsigned old = atomicAdd(&g_cnt, 1u);
            unsigned target = ep * (unsigned)NB;
            unsigned rel;
            if (old == target - 1u) {      // last arriver releases
                __threadfence();           // acquire all blocks' writes
                unsigned stop = 0;
                if (doCommit) {
                    stop = (__int_as_float(g_accbits) < TOLV) ? 1u : 0u;
                    g_accbits = 0;
                }
                __threadfence();
                rel = ep * 2u + stop;
                g_ep = rel;
            } else {
                do { rel = g_ep; } while ((int)(rel - ep * 2u) < 0);
                __threadfence();           // cumulative acquire
            }
            *sstop = (int)(rel & 1u);
        }
    }
    __syncthreads();                       // propagate visibility + sstop
    return *sstop != 0;
}

struct LineBlk {
    float s[NSIDE + 2];
    float o[NSIDE];
    float ob[NSIDE];
    float p[NSIDE];
    float q[NSIDE];
    unsigned char f_log[HALF + 2];
    unsigned char b_log[HALF + 2];
    TVState sf_end[NSEGS], sb_end[NSEGS];   // scanner end states (1..NSEGS-1)
    TVState sx_end[NSEGS], bx_end[NSEGS];   // chase-extension states
    unsigned char f_link[NSEGS], b_link[NSEGS];  // 1=coupled, 2=extension
    int f_done[NSEGS];                      // per-segment publish flags
    int b_done[NSEGS];
    int f_chase[NSEGS];                     // chase-complete flags (1..NSEGS-2)
    int b_chase[NSEGS];
    int se_done;
    int se_b;
};

#define VOL(x) (*(volatile int*)&(x))

// Exact checker for one direction: head segment, log-coupled chase with
// precomputed link-chain shortcuts, graceful serial fallback.
template<bool FWD>
__device__ void exact_chase(LineBlk& sh, const float* rcp, TVState& t,
                            float* out, unsigned char* log,
                            TVState* send, TVState* xend,
                            unsigned char* link, int* done, int* chase)
{
    init_state_at<FWD>(sh.s, t, 0);
    tv_scan<FWD, 0>(sh.s, out, rcp, t, SEG, BIGK, 0);
    int j = 1;
    while (t.k < HALF) {
        while (!VOL(done[j])) { }
        if (j >= 2) { while (!VOL(chase[j - 1])) { } }   // order seg-j writers
        __threadfence_block();
        if (tv_scan<FWD, 2>(sh.s, out, rcp, t, (j + 1) * SEG, BIGK, log)) {
            int jj = (t.k0 - 1) / SEG;        // owner of matched restart
            t = send[jj];                      // truth at end of segment jj
            bool manual = false;
            while (t.k < HALF && !manual) {    // walk precomputed links
                while (!VOL(chase[jj])) { }
                __threadfence_block();
                if (link[jj] == 1) { jj += 1; t = send[jj]; }
                else               { t = xend[jj]; jj += 1; manual = true; }
            }
            j = jj + 1;                        // next segment for manual chase
        } else {
            j += 1;                            // fell through without coupling
        }
    }
}

// One full line solve using 16 scanner threads (one per warp within the line's
// 512 threads). Spec scanners publish + chase their right neighbor in
// parallel; exact checkers pipeline behind them and walk the link chain.
__device__ __forceinline__ void solve_line(LineBlk& sh, const float* rcp,
                                           int lt, TVState& tf, TVState& tb)
{
    const int w = lt >> 5;
    if ((lt & 31) != 0) return;

    if (w == 0) {
        // ---- exact forward ----
        exact_chase<true>(sh, rcp, tf, sh.o, sh.f_log, sh.sf_end, sh.sx_end,
                          sh.f_link, sh.f_done, sh.f_chase);
        // ---- stage C: close the middle gap (needs backward frontier) ----
        while (!VOL(sh.se_done)) { }
        __threadfence_block();
        tv_scan<true, 0>(sh.s, sh.o, rcp, tf, NSIDE, VOL(sh.se_b), 0);
    } else if (w < NSEGS) {
        // ---- speculative forward, segment w; then chase segment w+1 ----
        TVState t; init_state_at<true>(sh.s, t, w * SEG);
        tv_scan<true, 1>(sh.s, sh.o, rcp, t, (w + 1) * SEG, BIGK, sh.f_log);
        sh.sf_end[w] = t;
        __threadfence_block();
        VOL(sh.f_done[w]) = 1;
        if (w < NSEGS - 1) {
            while (!VOL(sh.f_done[w + 1])) { }
            __threadfence_block();
            if (tv_scan<true, 2>(sh.s, sh.o, rcp, t, (w + 2) * SEG, BIGK, sh.f_log))
                sh.f_link[w] = 1;              // coupled to scanner w+1
            else { sh.sx_end[w] = t; sh.f_link[w] = 2; }   // extension state
            __threadfence_block();
            VOL(sh.f_chase[w]) = 1;
        }
    } else if (w == NSEGS) {
        // ---- exact backward ----
        exact_chase<false>(sh, rcp, tb, sh.ob, sh.b_log, sh.sb_end, sh.bx_end,
                           sh.b_link, sh.b_done, sh.b_chase);
        VOL(sh.se_b) = NSIDE - tb.k0;          // first finalized bwd position
        __threadfence_block();
        VOL(sh.se_done) = 1;
    } else {
        // ---- speculative backward, segment w-NSEGS; then chase next ----
        int j = w - NSEGS;
        TVState t; init_state_at<false>(sh.s, t, j * SEG);
        tv_scan<false, 1>(sh.s, sh.ob, rcp, t, (j + 1) * SEG, BIGK, sh.b_log);
        sh.sb_end[j] = t;
        __threadfence_block();
        VOL(sh.b_done[j]) = 1;
        if (j < NSEGS - 1) {
            while (!VOL(sh.b_done[j + 1])) { }
            __threadfence_block();
            if (tv_scan<false, 2>(sh.s, sh.ob, rcp, t, (j + 2) * SEG, BIGK, sh.b_log))
                sh.b_link[j] = 1;
            else { sh.bx_end[j] = t; sh.b_link[j] = 2; }
            __threadfence_block();
            VOL(sh.b_chase[j]) = 1;
        }
    }
}

__global__ void __launch_bounds__(NT, 1)
tv2d_persistent(const float* __restrict__ X, float* __restrict__ x)
{
    __shared__ LineBlk sh[2];
    __shared__ float rcp_s[NSIDE];
    __shared__ float swm[NT / 32];
    __shared__ int sstop;
    const int tid  = threadIdx.x;
    const int line = tid >> 9;           // 0 or 1
    const int lt   = tid & (NTL - 1);    // tid within line
    const int lane = tid & 31;
    const int b    = blockIdx.x * 2 + line;   // owned column/row index
    const bool io  = (lt < NSIDE);
    unsigned ep = g_ep >> 1;             // unpack epoch (stable at launch)
    TVState tf, tb;
    LineBlk& L = sh[line];

    if (io) {
        L.p[lt] = 0.0f;
        L.q[lt] = 0.0f;
        if (line == 0) rcp_s[lt] = 1.0f / (float)(lt + 1);
    }
    if (lt == 0) { L.s[NSIDE] = 0.0f; L.s[NSIDE + 1] = 0.0f; }

    for (int it = 0; it < NITER; it++) {
        // ================= column phase: line owns column b =================
        if (io) {
            float xv = (it == 0) ? X[lt * NSIDE + b] : g_xT[b * NSIDE + lt];
            L.s[lt] = xv + L.p[lt];
            if (lt <= HALF - SEG) {       // clear restart logs [SEG, HALF]
                L.f_log[SEG + lt] = 0;
                L.b_log[SEG + lt] = 0;
            }
            if (lt < NSEGS) {
                L.f_done[lt] = 0;  L.b_done[lt] = 0;
                L.f_chase[lt] = 0; L.b_chase[lt] = 0;
            }
            if (lt == 0)    { L.se_done = 0; }
        }
        __syncthreads();

        solve_line(L, rcp_s, lt, tf, tb);
        __syncthreads();

        if (io) {
            int eb = L.se_b;
            float ov = (lt >= eb) ? L.ob[lt] : L.o[lt];
            L.p[lt] = L.s[lt] - ov;
            g_y[lt * NSIDE + b] = ov;     // strided column write
        }
        gridbar(ep, false, swm, &sstop);

        // ================= row phase: line owns row b =======================
        if (io) {
            L.s[lt] = g_y[b * NSIDE + lt] + L.q[lt];
            if (lt <= HALF - SEG) {
                L.f_log[SEG + lt] = 0;
                L.b_log[SEG + lt] = 0;
            }
            if (lt < NSEGS) {
                L.f_done[lt] = 0;  L.b_done[lt] = 0;
                L.f_chase[lt] = 0; L.b_chase[lt] = 0;
            }
            if (lt == 0)    { L.se_done = 0; }
        }
        __syncthreads();

        solve_line(L, rcp_s, lt, tf, tb);
        __syncthreads();

        float m = 0.0f;
        if (io) {
            int eb = L.se_b;
            float ov = (lt >= eb) ? L.ob[lt] : L.o[lt];
            float sv = L.s[lt];
            float qo = L.q[lt];
            L.q[lt] = sv - ov;
            x[b * NSIDE + lt] = ov;       // d_out (coalesced)
            g_xT[lt * NSIDE + b] = ov;    // transposed mirror
            m = fabsf((sv - qo) - ov);    // |y - x2|
        }
#pragma unroll
        for (int off = 16; off; off >>= 1)
            m = fmaxf(m, __shfl_xor_sync(0xffffffffu, m, off));
        if (lane == 0) swm[tid >> 5] = m;     // all 32 warps write a slot

        if (gridbar(ep, true, swm, &sstop)) break;   // DR converged
    }
}

extern "C" void kernel_launch(void* const* d_in, const int* in_sizes, int n_in,
                              void* d_out, int out_size)
{
    const float* X = (const float*)d_in[0];
    float* x = (float*)d_out;
    tv2d_persistent<<<NB, NT>>>(X, x);
}